// round 2
// baseline (speedup 1.0000x reference)
#include <cuda_runtime.h>
#include <cuda_bf16.h>

#define T_SEQ   256
#define HID     128
#define BATCH   1024
#define VOCABN  60
#define NCTA    148
#define RPG     4          // row slots per group (2 groups of 128 threads)

// ---------------- device scratch (no allocations allowed) ----------------
__device__ float g_last[BATCH * HID];     // h_{len-1} per row
__device__ float g_P[VOCABN * HID];       // P = emb @ W_ih^T
__device__ int   g_perm[BATCH];           // rows sorted by length (ascending)

// packed f32x2 FMA: acc.xy += a.xy * b.xy   (PTX-only FFMA2 on sm_10x)
#define FMA2(acc, a, b) \
    asm("fma.rn.f32x2 %0, %1, %2, %0;" : "+l"(acc) : "l"(a), "l"(b))
#define UNPACK2(lo, hi, v) \
    asm("mov.b64 {%0,%1}, %2;" : "=f"(lo), "=f"(hi) : "l"(v))

__device__ __forceinline__ float tanh_fast(float z) {
    // tanh(z) = 1 - 2/(exp(2z)+1); exp->inf and exp->0 limits are exact.
    float e = __expf(2.0f * z);
    return 1.0f - __fdividef(2.0f, e + 1.0f);
}

// ---------------- kernel 1: counting sort of rows by length ----------------
__global__ void sort_kernel(const int* __restrict__ lengths) {
    __shared__ int hist[257];
    __shared__ int scan[257];
    __shared__ int cnt[257];
    int tid = threadIdx.x;                 // 1024 threads == 1024 rows

    if (tid < 257) hist[tid] = 0;
    __syncthreads();
    atomicAdd(&hist[lengths[tid]], 1);     // len in [1,256]
    __syncthreads();
    if (tid <= 256) scan[tid] = hist[tid];
    __syncthreads();
    for (int d = 1; d <= 256; d <<= 1) {   // inclusive scan (Hillis-Steele)
        int val = 0;
        if (tid <= 256 && tid >= d) val = scan[tid - d];
        __syncthreads();
        if (tid <= 256) scan[tid] += val;
        __syncthreads();
    }
    if (tid <= 256) cnt[tid] = (tid == 0) ? 0 : scan[tid - 1];  // exclusive base
    __syncthreads();
    int p = atomicAdd(&cnt[lengths[tid]], 1);
    g_perm[p] = tid;
}

// ---------------- kernel 2: P = emb @ W_ih^T  (60 x 128) ----------------
__global__ void prep_P(const float* __restrict__ emb, const float* __restrict__ W_ih) {
    __shared__ float se[HID];
    int v = blockIdx.x;
    int j = threadIdx.x;
    se[j] = emb[v * HID + j];
    __syncthreads();
    const float* wr = W_ih + j * HID;
    float s = 0.0f;
#pragma unroll
    for (int k = 0; k < HID; k++) s += se[k] * wr[k];
    g_P[v * HID + j] = s;
}

// ---------------- kernel 3: main RNN ----------------
// 148 CTAs x 256 threads. Two independent groups of 128 threads; each group
// runs up to RPG rows. Thread j of a group owns output lane j and holds
// W_hh row j in 64 packed f32x2 registers. One named barrier per group per step.
__global__ __launch_bounds__(256, 1) void rnn_main(
    const int* __restrict__ x, const int* __restrict__ lengths,
    const float* __restrict__ W_hh)
{
    __shared__ float shP[VOCABN * HID];              // 30 KB
    __shared__ float sh_h[2][RPG][2][HID];           // 4 KB (double-buffered h)
    __shared__ int   sh_tok[2][RPG][T_SEQ];          // 8 KB

    int tid = threadIdx.x;
    int g   = tid >> 7;          // group 0/1
    int j   = tid & 127;         // output lane
    int c   = blockIdx.x;

    // stage P into shared
    for (int i = tid; i < VOCABN * HID; i += 256) shP[i] = g_P[i];

    // row assignment: boustrophedon over sorted quantiles for CTA balance
    int row[RPG], len[RPG];
    int maxlen = 0;
#pragma unroll
    for (int s = 0; s < RPG; s++) {
        int ord = s * 2 + g;
        int idx = NCTA * ord + ((ord & 1) ? (NCTA - 1 - c) : c);
        if (idx < BATCH) {
            int r = g_perm[idx];
            row[s] = r;
            len[s] = lengths[r];
        } else { row[s] = -1; len[s] = 0; }
        maxlen = max(maxlen, len[s]);
        sh_h[g][s][0][j] = 0.0f;             // h_{-1} = 0
        if (row[s] >= 0) {
            sh_tok[g][s][j]       = x[row[s] * T_SEQ + j];
            sh_tok[g][s][j + 128] = x[row[s] * T_SEQ + 128 + j];
        }
    }

    // weight-stationary: W_hh row j as 64 packed f32x2 (one-time load, L2-resident)
    unsigned long long w[64];
    const unsigned long long* Wq =
        reinterpret_cast<const unsigned long long*>(W_hh) + (size_t)j * 64;
#pragma unroll
    for (int i = 0; i < 64; i++) w[i] = Wq[i];

    __syncthreads();

    for (int t = 0; t < maxlen; t++) {
        int cur = t & 1, nxt = cur ^ 1;
#pragma unroll
        for (int s = 0; s < RPG; s++) {
            if (t < len[s]) {                          // uniform within group
                int tok = sh_tok[g][s][t];
                float base = shP[tok * HID + j];
                const unsigned long long* hq =
                    reinterpret_cast<const unsigned long long*>(sh_h[g][s][cur]);
                unsigned long long a0 = 0ull, a1 = 0ull, a2 = 0ull, a3 = 0ull;
#pragma unroll
                for (int i = 0; i < 64; i += 4) {      // 64 FFMA2 + 64 LDS.64
                    FMA2(a0, w[i + 0], hq[i + 0]);
                    FMA2(a1, w[i + 1], hq[i + 1]);
                    FMA2(a2, w[i + 2], hq[i + 2]);
                    FMA2(a3, w[i + 3], hq[i + 3]);
                }
                float lo, hi, z = base;
                UNPACK2(lo, hi, a0); z += lo + hi;
                UNPACK2(lo, hi, a1); z += lo + hi;
                UNPACK2(lo, hi, a2); z += lo + hi;
                UNPACK2(lo, hi, a3); z += lo + hi;
                float h = tanh_fast(z);
                sh_h[g][s][nxt][j] = h;
                if (t == len[s] - 1)                   // retire row
                    g_last[row[s] * HID + j] = h;
            }
        }
        // per-group barrier (ids 1 and 2), 128 threads each
        asm volatile("bar.sync %0, 128;" :: "r"(g + 1) : "memory");
    }
}

// ---------------- kernel 4: out = h_last @ W_fc^T + b_fc ----------------
__global__ void fc_kernel(const float* __restrict__ W_fc,
                          const float* __restrict__ b_fc,
                          float* __restrict__ out)
{
    __shared__ float sh[HID];
    int b = blockIdx.x, tid = threadIdx.x;   // 64 threads
    sh[tid]      = g_last[b * HID + tid];
    sh[tid + 64] = g_last[b * HID + 64 + tid];
    __syncthreads();
    if (tid < VOCABN) {
        const float* wr = W_fc + tid * HID;
        float acc = b_fc[tid];
#pragma unroll
        for (int k = 0; k < HID; k++) acc += sh[k] * wr[k];
        out[b * VOCABN + tid] = acc;
    }
}

// ---------------- launch ----------------
extern "C" void kernel_launch(void* const* d_in, const int* in_sizes, int n_in,
                              void* d_out, int out_size) {
    const int*   x       = (const int*)d_in[0];
    const int*   lengths = (const int*)d_in[1];
    const float* emb     = (const float*)d_in[2];
    const float* W_ih    = (const float*)d_in[3];
    const float* W_hh    = (const float*)d_in[4];
    const float* W_fc    = (const float*)d_in[5];
    const float* b_fc    = (const float*)d_in[6];
    float*       out     = (float*)d_out;

    sort_kernel<<<1, 1024>>>(lengths);
    prep_P<<<VOCABN, HID>>>(emb, W_ih);
    rnn_main<<<NCTA, 256>>>(x, lengths, W_hh);
    fc_kernel<<<BATCH, 64>>>(W_fc, b_fc, out);
}

// round 3
// speedup vs baseline: 1.2164x; 1.2164x over previous
#include <cuda_runtime.h>
#include <cuda_bf16.h>

#define T_SEQ   256
#define HID     128
#define BATCH   1024
#define VOCABN  60
#define NCTA    152
#define RPG     4          // row slots per group (2 groups of 128 threads)
#define FC_RPB  16         // batch rows per fc CTA

// ---------------- device scratch (no allocations allowed) ----------------
__device__ float g_last[BATCH * HID];     // h_{len-1} per row
__device__ float g_P[VOCABN * HID];       // P = emb @ W_ih^T
__device__ int   g_perm[BATCH];           // rows sorted by length (ascending)

// packed f32x2 ops (PTX-only on sm_10x)
#define FMA2(acc, a, b) \
    asm("fma.rn.f32x2 %0, %1, %2, %0;" : "+l"(acc) : "l"(a), "l"(b))
#define ADD2(dst, a, b) \
    asm("add.rn.f32x2 %0, %1, %2;" : "=l"(dst) : "l"(a), "l"(b))
#define UNPACK2(lo, hi, v) \
    asm("mov.b64 {%0,%1}, %2;" : "=f"(lo), "=f"(hi) : "l"(v))

__device__ __forceinline__ float tanh_fast(float z) {
    // tanh(z) = 1 - 2/(exp(2z)+1); both saturation limits are exact.
    float e = __expf(2.0f * z);
    return 1.0f - __fdividef(2.0f, e + 1.0f);
}

// ---------------- kernel 1: fused prep ----------------
// blocks 0..59: P = emb @ W_ih^T row v. block 60: counting sort of rows by length.
__global__ __launch_bounds__(1024) void prep_sort(
    const int* __restrict__ lengths,
    const float* __restrict__ emb, const float* __restrict__ W_ih)
{
    int tid = threadIdx.x;
    if (blockIdx.x < VOCABN) {
        __shared__ float se[HID];
        int v = blockIdx.x;
        if (tid < HID) se[tid] = emb[v * HID + tid];
        __syncthreads();
        if (tid < HID) {
            const float* wr = W_ih + tid * HID;
            float s = 0.0f;
#pragma unroll
            for (int k = 0; k < HID; k++) s += se[k] * wr[k];
            g_P[v * HID + tid] = s;
        }
    } else {
        __shared__ int hist[257];
        __shared__ int scan[257];
        __shared__ int cnt[257];
        if (tid < 257) hist[tid] = 0;
        __syncthreads();
        atomicAdd(&hist[lengths[tid]], 1);     // len in [1,256]
        __syncthreads();
        if (tid <= 256) scan[tid] = hist[tid];
        __syncthreads();
        for (int d = 1; d <= 256; d <<= 1) {   // inclusive scan
            int val = 0;
            if (tid <= 256 && tid >= d) val = scan[tid - d];
            __syncthreads();
            if (tid <= 256) scan[tid] += val;
            __syncthreads();
        }
        if (tid <= 256) cnt[tid] = (tid == 0) ? 0 : scan[tid - 1];  // exclusive
        __syncthreads();
        int p = atomicAdd(&cnt[lengths[tid]], 1);
        g_perm[p] = tid;
    }
}

// ---------------- kernel 2: main RNN ----------------
// 152 CTAs x 256 threads. Two groups of 128 threads, per-group named barrier.
// Thread j of a group owns output lane j; W_hh row j lives in 64 packed f32x2 regs.
// h read via broadcast LDS.128 (ulonglong2 = two FFMA2 operands, no repack).
__global__ __launch_bounds__(256, 1) void rnn_main(
    const int* __restrict__ x, const int* __restrict__ lengths,
    const float* __restrict__ W_hh)
{
    __shared__ float shP[VOCABN * HID];                        // 30 KB
    __shared__ __align__(16) float sh_h[2][RPG][2][HID];       // 8 KB double-buffered
    __shared__ int sh_tok[2][RPG][T_SEQ];                      // 8 KB

    int tid = threadIdx.x;
    int g   = tid >> 7;          // group 0/1
    int j   = tid & 127;         // output lane
    int c   = blockIdx.x;

    for (int i = tid; i < VOCABN * HID; i += 256) shP[i] = g_P[i];

    // band (quantile) assignment: g0 gets bands {0,1,4,5}, g1 gets {2,3,6}
    // (band 6 holds the longest rows; g1 has less total work -> smaller tail).
    // Boustrophedon +-c within each band balances total work across CTAs.
    const int ORD0[RPG] = {0, 1, 4, 5};
    const int ORD1[RPG] = {2, 3, 6, 7};   // ord 7 -> idx >= 1064 -> empty slot

    int row[RPG], len[RPG];
    int maxlen = 0;
#pragma unroll
    for (int s = 0; s < RPG; s++) {
        int ord = g ? ORD1[s] : ORD0[s];
        int idx = NCTA * ord + ((ord & 1) ? (NCTA - 1 - c) : c);
        if (idx < BATCH) {
            int r = g_perm[idx];
            row[s] = r;
            len[s] = lengths[r];
        } else { row[s] = -1; len[s] = 0; }
        maxlen = max(maxlen, len[s]);
        sh_h[g][s][0][j] = 0.0f;
        if (row[s] >= 0) {
            sh_tok[g][s][j]       = x[row[s] * T_SEQ + j];
            sh_tok[g][s][j + 128] = x[row[s] * T_SEQ + 128 + j];
        }
    }

    // weight-stationary: W_hh row j as 64 packed f32x2
    unsigned long long w[64];
    const ulonglong2* Wq = reinterpret_cast<const ulonglong2*>(W_hh) + (size_t)j * 32;
#pragma unroll
    for (int i = 0; i < 32; i++) {
        ulonglong2 t = Wq[i];
        w[2 * i]     = t.x;
        w[2 * i + 1] = t.y;
    }

    __syncthreads();

    for (int t = 0; t < maxlen; t++) {
        int cur = t & 1, nxt = cur ^ 1;
#pragma unroll
        for (int s = 0; s < RPG; s++) {
            if (t < len[s]) {                          // uniform within group
                int tok = sh_tok[g][s][t];
                float base = shP[tok * HID + j];
                const ulonglong2* hq =
                    reinterpret_cast<const ulonglong2*>(sh_h[g][s][cur]);
                unsigned long long a0 = 0ull, a1 = 0ull, a2 = 0ull, a3 = 0ull;
#pragma unroll
                for (int i = 0; i < 32; i += 2) {      // 32 LDS.128 + 64 FFMA2
                    ulonglong2 v0 = hq[i];
                    ulonglong2 v1 = hq[i + 1];
                    FMA2(a0, w[2 * i + 0], v0.x);
                    FMA2(a1, w[2 * i + 1], v0.y);
                    FMA2(a2, w[2 * i + 2], v1.x);
                    FMA2(a3, w[2 * i + 3], v1.y);
                }
                ADD2(a0, a0, a1);
                ADD2(a2, a2, a3);
                ADD2(a0, a0, a2);
                float lo, hi;
                UNPACK2(lo, hi, a0);
                float h = tanh_fast(base + lo + hi);
                sh_h[g][s][nxt][j] = h;
                if (t == len[s] - 1)                   // retire row
                    g_last[row[s] * HID + j] = h;
            }
        }
        asm volatile("bar.sync %0, 128;" :: "r"(g + 1) : "memory");
    }
}

// ---------------- kernel 3: out = h_last @ W_fc^T + b_fc ----------------
// 64 CTAs x 256 threads; W_fc staged once per CTA in smem; 16 batch rows/CTA;
// each thread: 1 vocab col x 4 batch rows, conflict-free padded smem.
__global__ __launch_bounds__(256) void fc_kernel(
    const float* __restrict__ W_fc, const float* __restrict__ b_fc,
    float* __restrict__ out)
{
    __shared__ __align__(16) float sW[VOCABN][HID + 4];
    __shared__ __align__(16) float sH[FC_RPB][HID + 4];
    int tid = threadIdx.x;
    int b0  = blockIdx.x * FC_RPB;

    for (int i = tid; i < VOCABN * HID; i += 256) sW[i / HID][i % HID] = W_fc[i];
    for (int i = tid; i < FC_RPB * HID; i += 256) sH[i / HID][i % HID] = g_last[(size_t)b0 * HID + i];
    __syncthreads();

    int v  = tid >> 2;     // 0..63
    int bq = tid & 3;
    if (v < VOCABN) {
        float acc0 = 0.f, acc1 = 0.f, acc2 = 0.f, acc3 = 0.f;
#pragma unroll
        for (int k = 0; k < HID; k += 4) {
            float4 wv = *reinterpret_cast<const float4*>(&sW[v][k]);
            float4 h0 = *reinterpret_cast<const float4*>(&sH[bq * 4 + 0][k]);
            float4 h1 = *reinterpret_cast<const float4*>(&sH[bq * 4 + 1][k]);
            float4 h2 = *reinterpret_cast<const float4*>(&sH[bq * 4 + 2][k]);
            float4 h3 = *reinterpret_cast<const float4*>(&sH[bq * 4 + 3][k]);
            acc0 += wv.x * h0.x + wv.y * h0.y + wv.z * h0.z + wv.w * h0.w;
            acc1 += wv.x * h1.x + wv.y * h1.y + wv.z * h1.z + wv.w * h1.w;
            acc2 += wv.x * h2.x + wv.y * h2.y + wv.z * h2.z + wv.w * h2.w;
            acc3 += wv.x * h3.x + wv.y * h3.y + wv.z * h3.z + wv.w * h3.w;
        }
        float bias = b_fc[v];
        out[(size_t)(b0 + bq * 4 + 0) * VOCABN + v] = acc0 + bias;
        out[(size_t)(b0 + bq * 4 + 1) * VOCABN + v] = acc1 + bias;
        out[(size_t)(b0 + bq * 4 + 2) * VOCABN + v] = acc2 + bias;
        out[(size_t)(b0 + bq * 4 + 3) * VOCABN + v] = acc3 + bias;
    }
}

// ---------------- launch ----------------
extern "C" void kernel_launch(void* const* d_in, const int* in_sizes, int n_in,
                              void* d_out, int out_size) {
    const int*   x       = (const int*)d_in[0];
    const int*   lengths = (const int*)d_in[1];
    const float* emb     = (const float*)d_in[2];
    const float* W_ih    = (const float*)d_in[3];
    const float* W_hh    = (const float*)d_in[4];
    const float* W_fc    = (const float*)d_in[5];
    const float* b_fc    = (const float*)d_in[6];
    float*       out     = (float*)d_out;

    prep_sort<<<VOCABN + 1, 1024>>>(lengths, emb, W_ih);
    rnn_main<<<NCTA, 256>>>(x, lengths, W_hh);
    fc_kernel<<<BATCH / FC_RPB, 256>>>(W_fc, b_fc, out);
}